// round 2
// baseline (speedup 1.0000x reference)
#include <cuda_runtime.h>
#include <math.h>

// B=64, L=S=2048, H=8, E=64, MODES=64, O=64. NBH = B*H = 512.
#define PIT 68
#define SMEM_MID (6 * 64 * PIT * 4)

__device__ __align__(16) float g_basis[128 * 2048];   // rows 0-63 cos, 64-127 sin
__device__ __align__(16) float g_QF[512 * 8192];      // per bh: [128 m][64 e]
__device__ __align__(16) float g_KF[512 * 8192];
__device__ __align__(16) float g_G [512 * 8192];      // per bh: [64 o][128 k] folded coeffs

__global__ void fill_basis_kernel() {
    int idx = blockIdx.x * blockDim.x + threadIdx.x;
    if (idx >= 128 * 2048) return;
    int m = idx >> 11, s = idx & 2047;
    int ph = ((m & 63) * s) & 2047;  // exact integer phase
    double ang = (double)ph * (6.283185307179586476925286766559 / 2048.0);
    g_basis[idx] = (float)((m < 64) ? cos(ang) : sin(ang));
}

__device__ __forceinline__ float dot4(float4 a, float4 b) {
    return a.x * b.x + a.y * b.y + a.z * b.z + a.w * b.w;
}
__device__ __forceinline__ void kadd(float& acc, float& comp, float v) {
    float y = v - comp;
    float t = acc + y;
    comp = (t - acc) - y;
    acc = t;
}

// ----------------- stage 1: forward DFT. grid(512,2) block 256 ----------------
__global__ __launch_bounds__(256) void dft_kernel(const float* __restrict__ q,
                                                  const float* __restrict__ k) {
    int bh = blockIdx.x;
    const float* src = blockIdx.y ? k : q;
    float* dst = blockIdx.y ? g_KF : g_QF;
    int b = bh >> 3, h = bh & 7;
    const float* base = src + (size_t)b * 2048 * 512 + (size_t)h * 64;

    __shared__ float Wsm[32][132];  // [k][m]
    __shared__ float Xs[32][68];    // [k][e]
    int tid = threadIdx.x;
    int ty = tid >> 4, tx = tid & 15;   // ty: 8 m-rows, tx: 4 e-cols

    float acc[8][4], comp[8][4];
#pragma unroll
    for (int i = 0; i < 8; i++)
#pragma unroll
        for (int j = 0; j < 4; j++) { acc[i][j] = 0.f; comp[i][j] = 0.f; }

    for (int k0 = 0; k0 < 2048; k0 += 32) {
#pragma unroll
        for (int jj = 0; jj < 4; jj++) {
            int t4 = tid + jj * 256;
            int m = t4 >> 3, kc = (t4 & 7) * 4;
            float4 w = *(const float4*)&g_basis[m * 2048 + k0 + kc];
            Wsm[kc + 0][m] = w.x; Wsm[kc + 1][m] = w.y;
            Wsm[kc + 2][m] = w.z; Wsm[kc + 3][m] = w.w;
        }
#pragma unroll
        for (int jj = 0; jj < 2; jj++) {
            int t4 = tid + jj * 256;
            int l = t4 >> 4, e4 = (t4 & 15) * 4;
            *(float4*)&Xs[l][e4] = *(const float4*)&base[(size_t)(k0 + l) * 512 + e4];
        }
        __syncthreads();

        float part[8][4];
#pragma unroll
        for (int i = 0; i < 8; i++)
#pragma unroll
            for (int j = 0; j < 4; j++) part[i][j] = 0.f;
#pragma unroll
        for (int kk = 0; kk < 32; kk++) {
            float a[8];
#pragma unroll
            for (int i = 0; i < 8; i++) a[i] = Wsm[kk][ty * 8 + i];
            float4 b4 = *(float4*)&Xs[kk][tx * 4];
            float bb[4] = { b4.x, b4.y, b4.z, b4.w };
#pragma unroll
            for (int i = 0; i < 8; i++)
#pragma unroll
                for (int j = 0; j < 4; j++)
                    part[i][j] = fmaf(a[i], bb[j], part[i][j]);
        }
#pragma unroll
        for (int i = 0; i < 8; i++)
#pragma unroll
            for (int j = 0; j < 4; j++) kadd(acc[i][j], comp[i][j], part[i][j]);
        __syncthreads();
    }

    float* out = dst + (size_t)bh * 8192;
#pragma unroll
    for (int i = 0; i < 8; i++) {
        int m = ty * 8 + i;
        float4 v = make_float4(acc[i][0], acc[i][1], acc[i][2], acc[i][3]);
        *(float4*)&out[m * 64 + tx * 4] = v;
    }
}

// ----------------- stage 2: mid. grid 512, block 512, dyn smem ----------------
__global__ __launch_bounds__(512) void mid_kernel(const float* __restrict__ w1r,
                                                  const float* __restrict__ w1i) {
    extern __shared__ float smem[];
    float* Qc  = smem;               // -> reused as Vr
    float* Qs  = Qc  + 64 * PIT;     // -> reused as Vi
    float* Kc  = Qs  + 64 * PIT;
    float* Ks  = Kc  + 64 * PIT;
    float* TrT = Ks  + 64 * PIT;     // T transposed: [y][x]
    float* TiT = TrT + 64 * PIT;
    float* Vr  = Qc;
    float* Vi  = Qs;

    int bh = blockIdx.x, h = bh & 7;
    int tid = threadIdx.x;

    {
        const float* qf = g_QF + (size_t)bh * 8192;
        const float* kf = g_KF + (size_t)bh * 8192;
        for (int idx = tid; idx < 4096; idx += 512) {
            int m = idx >> 6, e = idx & 63;
            Qc[m * PIT + e] = qf[idx];
            Qs[m * PIT + e] = qf[4096 + idx];
            Kc[m * PIT + e] = kf[idx];
            Ks[m * PIT + e] = kf[4096 + idx];
        }
    }
    __syncthreads();

    // A[x,y] = sum_e (Qc-iQs)[x]·(Kc-iKs)[y]; T = ctanh(A); store T^T
    {
        int xg = (tid >> 4) * 2;     // 2 x rows
        int y0 = tid & 15;           // 4 y rows: y0, y0+16, y0+32, y0+48
        float ar[2][4], ai[2][4], car[2][4], cai[2][4];
#pragma unroll
        for (int i = 0; i < 2; i++)
#pragma unroll
            for (int j = 0; j < 4; j++) { ar[i][j] = ai[i][j] = car[i][j] = cai[i][j] = 0.f; }

        for (int e4 = 0; e4 < 64; e4 += 4) {
            float4 qc[2], qs[2], kc[4], ks[4];
#pragma unroll
            for (int i = 0; i < 2; i++) {
                qc[i] = *(float4*)&Qc[(xg + i) * PIT + e4];
                qs[i] = *(float4*)&Qs[(xg + i) * PIT + e4];
            }
#pragma unroll
            for (int j = 0; j < 4; j++) {
                kc[j] = *(float4*)&Kc[(y0 + j * 16) * PIT + e4];
                ks[j] = *(float4*)&Ks[(y0 + j * 16) * PIT + e4];
            }
#pragma unroll
            for (int i = 0; i < 2; i++)
#pragma unroll
                for (int j = 0; j < 4; j++) {
                    float pr = dot4(qc[i], kc[j]) - dot4(qs[i], ks[j]);
                    float pi = dot4(qc[i], ks[j]) + dot4(qs[i], kc[j]);
                    kadd(ar[i][j], car[i][j], pr);
                    kadd(ai[i][j], cai[i][j], -pi);
                }
        }
#pragma unroll
        for (int i = 0; i < 2; i++)
#pragma unroll
            for (int j = 0; j < 4; j++) {
                float a = ar[i][j], bv = ai[i][j];
                float ta = tanhf(a);
                float tb = tanf(bv);
                float ta2 = ta * ta, tb2 = tb * tb;
                float inv = 1.0f / fmaf(ta2, tb2, 1.0f);
                int y = y0 + j * 16;
                TrT[y * PIT + (xg + i)] = ta * (1.0f + tb2) * inv;
                TiT[y * PIT + (xg + i)] = tb * (1.0f - ta2) * inv;
            }
    }
    __syncthreads();

    // V[e,x] = sum_y T[x,y]*(Kc-iKs)[y,e]  (writes over Qc/Qs)
    {
        int eg = (tid >> 4) * 2;
        int xg = (tid & 15) * 4;
        float vr0[4] = {0,0,0,0}, vr1[4] = {0,0,0,0};
        float vi0[4] = {0,0,0,0}, vi1[4] = {0,0,0,0};
        for (int y = 0; y < 64; y++) {
            float kc0 = Kc[y * PIT + eg + 0], kc1 = Kc[y * PIT + eg + 1];
            float ks0 = Ks[y * PIT + eg + 0], ks1 = Ks[y * PIT + eg + 1];
            float4 t4 = *(float4*)&TrT[y * PIT + xg];
            float4 u4 = *(float4*)&TiT[y * PIT + xg];
            float tr[4] = { t4.x, t4.y, t4.z, t4.w };
            float ti[4] = { u4.x, u4.y, u4.z, u4.w };
#pragma unroll
            for (int j = 0; j < 4; j++) {
                vr0[j] = fmaf(tr[j], kc0, fmaf( ti[j], ks0, vr0[j]));
                vi0[j] = fmaf(ti[j], kc0, fmaf(-tr[j], ks0, vi0[j]));
                vr1[j] = fmaf(tr[j], kc1, fmaf( ti[j], ks1, vr1[j]));
                vi1[j] = fmaf(ti[j], kc1, fmaf(-tr[j], ks1, vi1[j]));
            }
        }
        __syncthreads();   // everyone done reading old Qc/Qs (aliased by Vr/Vi)
        *(float4*)&Vr[(eg + 0) * PIT + xg] = make_float4(vr0[0], vr0[1], vr0[2], vr0[3]);
        *(float4*)&Vr[(eg + 1) * PIT + xg] = make_float4(vr1[0], vr1[1], vr1[2], vr1[3]);
        *(float4*)&Vi[(eg + 0) * PIT + xg] = make_float4(vi0[0], vi0[1], vi0[2], vi0[3]);
        *(float4*)&Vi[(eg + 1) * PIT + xg] = make_float4(vi1[0], vi1[1], vi1[2], vi1[3]);
    }
    __syncthreads();

    // G[o,x] = sum_e V[e,x]*w1[h,e,o,x]; fold irfft coefficients; write g_G
    {
        int og = (tid >> 4) * 2;
        int xg = (tid & 15) * 4;
        float gr0[4] = {0,0,0,0}, gr1[4] = {0,0,0,0};
        float gi0[4] = {0,0,0,0}, gi1[4] = {0,0,0,0};
        const float* wr = w1r + (size_t)h * 262144;
        const float* wi = w1i + (size_t)h * 262144;
        for (int e = 0; e < 64; e++) {
            float4 a4 = *(float4*)&Vr[e * PIT + xg];
            float4 b4 = *(float4*)&Vi[e * PIT + xg];
            float vr[4] = { a4.x, a4.y, a4.z, a4.w };
            float vi[4] = { b4.x, b4.y, b4.z, b4.w };
            const float* wrb = wr + e * 4096;
            const float* wib = wi + e * 4096;
            float4 r0 = *(const float4*)&wrb[(og + 0) * 64 + xg];
            float4 r1 = *(const float4*)&wrb[(og + 1) * 64 + xg];
            float4 s0 = *(const float4*)&wib[(og + 0) * 64 + xg];
            float4 s1 = *(const float4*)&wib[(og + 1) * 64 + xg];
            float w0r[4] = { r0.x, r0.y, r0.z, r0.w }, w1rr[4] = { r1.x, r1.y, r1.z, r1.w };
            float w0i[4] = { s0.x, s0.y, s0.z, s0.w }, w1ii[4] = { s1.x, s1.y, s1.z, s1.w };
#pragma unroll
            for (int j = 0; j < 4; j++) {
                gr0[j] = fmaf(vr[j], w0r[j],  fmaf(-vi[j], w0i[j],  gr0[j]));
                gi0[j] = fmaf(vr[j], w0i[j],  fmaf( vi[j], w0r[j],  gi0[j]));
                gr1[j] = fmaf(vr[j], w1rr[j], fmaf(-vi[j], w1ii[j], gr1[j]));
                gi1[j] = fmaf(vr[j], w1ii[j], fmaf( vi[j], w1rr[j], gi1[j]));
            }
        }
        const float sc = 1.862645149230957e-09f;  // 1/(2048*512*512)
        float* gout = g_G + (size_t)bh * 8192;
#pragma unroll
        for (int j = 0; j < 4; j++) {
            int m = xg + j;
            float cf = (m == 0) ? sc : 2.0f * sc;
            gout[(og + 0) * 128 + m]      = cf * gr0[j];
            gout[(og + 1) * 128 + m]      = cf * gr1[j];
            gout[(og + 0) * 128 + 64 + m] = -2.0f * sc * gi0[j];
            gout[(og + 1) * 128 + 64 + m] = -2.0f * sc * gi1[j];
        }
    }
}

// ----------------- stage 3: inverse DFT. grid(16,512) block 256 ---------------
__global__ __launch_bounds__(256) void idft_kernel(float* __restrict__ out) {
    int bh = blockIdx.y;
    int l0 = blockIdx.x * 128;
    __shared__ float Gst[128][68];  // [k][o]
    __shared__ float Ws[16][132];   // [k][l]
    int tid = threadIdx.x;
    const float* g = g_G + (size_t)bh * 8192;
#pragma unroll
    for (int jj = 0; jj < 8; jj++) {
        int t4 = tid + jj * 256;          // 2048 float4s
        int o = t4 >> 5, kc = (t4 & 31) * 4;
        float4 v = *(const float4*)&g[o * 128 + kc];
        Gst[kc + 0][o] = v.x; Gst[kc + 1][o] = v.y;
        Gst[kc + 2][o] = v.z; Gst[kc + 3][o] = v.w;
    }

    int ty = tid >> 5, tx = tid & 31;   // 8 o-rows, 4 l-cols
    float acc[8][4];
#pragma unroll
    for (int i = 0; i < 8; i++)
#pragma unroll
        for (int j = 0; j < 4; j++) acc[i][j] = 0.f;

    for (int k0 = 0; k0 < 128; k0 += 16) {
        __syncthreads();
#pragma unroll
        for (int jj = 0; jj < 2; jj++) {
            int t4 = tid + jj * 256;
            int kk = t4 >> 5, ll = (t4 & 31) * 4;
            *(float4*)&Ws[kk][ll] = *(const float4*)&g_basis[(k0 + kk) * 2048 + l0 + ll];
        }
        __syncthreads();
#pragma unroll
        for (int kk = 0; kk < 16; kk++) {
            float4 w4 = *(float4*)&Ws[kk][tx * 4];
            float wv[4] = { w4.x, w4.y, w4.z, w4.w };
            float a[8];
#pragma unroll
            for (int i = 0; i < 8; i++) a[i] = Gst[k0 + kk][ty * 8 + i];
#pragma unroll
            for (int i = 0; i < 8; i++)
#pragma unroll
                for (int j = 0; j < 4; j++)
                    acc[i][j] = fmaf(a[i], wv[j], acc[i][j]);
        }
    }

    float* ob = out + ((size_t)bh * 64) * 2048 + l0;
#pragma unroll
    for (int i = 0; i < 8; i++) {
        int o = ty * 8 + i;
        *(float4*)&ob[(size_t)o * 2048 + tx * 4] =
            make_float4(acc[i][0], acc[i][1], acc[i][2], acc[i][3]);
    }
}

extern "C" void kernel_launch(void* const* d_in, const int* in_sizes, int n_in,
                              void* d_out, int out_size) {
    const float* q   = (const float*)d_in[0];
    const float* k   = (const float*)d_in[1];
    const float* w1r = (const float*)d_in[3];
    const float* w1i = (const float*)d_in[4];
    float* out = (float*)d_out;

    static bool attr_set = false;
    if (!attr_set) {
        cudaFuncSetAttribute(mid_kernel, cudaFuncAttributeMaxDynamicSharedMemorySize, SMEM_MID);
        attr_set = true;
    }

    fill_basis_kernel<<<512, 512>>>();
    dft_kernel<<<dim3(512, 2), 256>>>(q, k);
    mid_kernel<<<512, 512, SMEM_MID>>>(w1r, w1i);
    idft_kernel<<<dim3(16, 512), 256>>>(out);
}

// round 6
// speedup vs baseline: 1.6434x; 1.6434x over previous
#include <cuda_runtime.h>
#include <math.h>

// B=64, L=S=2048, H=8, E=64, MODES=64, O=64. NBH = B*H = 512.
#define PIT 68
#define SMEM_MID (6 * 64 * PIT * 4)

__device__ __align__(16) float g_basis[128 * 2048];   // rows 0-63 cos(2pi m s/2048), 64-127 sin
__device__ __align__(16) float g_QF[512 * 8192];      // per bh: [128 m][64 e]
__device__ __align__(16) float g_KF[512 * 8192];
__device__ __align__(16) float g_G [512 * 8192];      // per bh: [64 o][128 k] folded coeffs

__global__ void fill_basis_kernel() {
    int idx = blockIdx.x * blockDim.x + threadIdx.x;
    if (idx >= 128 * 2048) return;
    int m = idx >> 11, s = idx & 2047;
    int ph = ((m & 63) * s) & 2047;  // exact integer phase
    double ang = (double)ph * (6.283185307179586476925286766559 / 2048.0);
    g_basis[idx] = (float)((m < 64) ? cos(ang) : sin(ang));
}

__device__ __forceinline__ float dot4(float4 a, float4 b) {
    return a.x * b.x + a.y * b.y + a.z * b.z + a.w * b.w;
}
__device__ __forceinline__ void kadd(float& acc, float& comp, float v) {
    float y = v - comp;
    float t = acc + y;
    comp = (t - acc) - y;
    acc = t;
}

// ---------- stage 1: folded forward DFT. grid(512,2) block 256 ----------
// cos rows use P[t]=x[t]+x[2048-t], sin rows use M[t]=x[t]-x[2048-t], t=0..1023
// (P[0]=x[0], M[0]=0); epilogue adds (-1)^m * x[1024] to cos rows.
__global__ __launch_bounds__(256) void dft_kernel(const float* __restrict__ q,
                                                  const float* __restrict__ k) {
    int bh = blockIdx.x;
    const float* src = blockIdx.y ? k : q;
    float* dst = blockIdx.y ? g_KF : g_QF;
    int b = bh >> 3, h = bh & 7;
    const float* base = src + (size_t)b * 2048 * 512 + (size_t)h * 64;

    __shared__ float Wsm[32][132];  // [t][m] basis tile (all 128 rows)
    __shared__ float Ps[32][68];    // [t][e]
    __shared__ float Ms[32][68];
    int tid = threadIdx.x;
    int ty = tid >> 4, tx = tid & 15;   // ty: 8 m-rows; tx: 4 e-cols

    float acc[8][4], comp[8][4];
#pragma unroll
    for (int i = 0; i < 8; i++)
#pragma unroll
        for (int j = 0; j < 4; j++) { acc[i][j] = 0.f; comp[i][j] = 0.f; }

    for (int k0 = 0; k0 < 1024; k0 += 32) {
        // basis tile (transpose into smem): columns t=k0..k0+31, rows 0..127
#pragma unroll
        for (int jj = 0; jj < 4; jj++) {
            int t4 = tid + jj * 256;
            int m = t4 >> 3, kc = (t4 & 7) * 4;
            float4 w = *(const float4*)&g_basis[m * 2048 + k0 + kc];
            Wsm[kc + 0][m] = w.x; Wsm[kc + 1][m] = w.y;
            Wsm[kc + 2][m] = w.z; Wsm[kc + 3][m] = w.w;
        }
        // P/M tiles from x[t] and x[2048-t]
#pragma unroll
        for (int jj = 0; jj < 2; jj++) {
            int t4 = tid + jj * 256;
            int l = t4 >> 4, e4 = (t4 & 15) * 4;
            int t = k0 + l;
            float4 fa = *(const float4*)&base[(size_t)t * 512 + e4];
            float4 p, m4;
            if (t == 0) {
                p = fa; m4 = make_float4(0.f, 0.f, 0.f, 0.f);
            } else {
                float4 fb = *(const float4*)&base[(size_t)(2048 - t) * 512 + e4];
                p  = make_float4(fa.x + fb.x, fa.y + fb.y, fa.z + fb.z, fa.w + fb.w);
                m4 = make_float4(fa.x - fb.x, fa.y - fb.y, fa.z - fb.z, fa.w - fb.w);
            }
            *(float4*)&Ps[l][e4] = p;
            *(float4*)&Ms[l][e4] = m4;
        }
        __syncthreads();

        const float (*Xop)[68] = (ty < 8) ? Ps : Ms;   // cos rows vs sin rows
        float part[8][4];
#pragma unroll
        for (int i = 0; i < 8; i++)
#pragma unroll
            for (int j = 0; j < 4; j++) part[i][j] = 0.f;
#pragma unroll
        for (int kk = 0; kk < 32; kk++) {
            float a[8];
#pragma unroll
            for (int i = 0; i < 8; i++) a[i] = Wsm[kk][ty * 8 + i];
            float4 b4 = *(const float4*)&Xop[kk][tx * 4];
            float bb[4] = { b4.x, b4.y, b4.z, b4.w };
#pragma unroll
            for (int i = 0; i < 8; i++)
#pragma unroll
                for (int j = 0; j < 4; j++)
                    part[i][j] = fmaf(a[i], bb[j], part[i][j]);
        }
#pragma unroll
        for (int i = 0; i < 8; i++)
#pragma unroll
            for (int j = 0; j < 4; j++) kadd(acc[i][j], comp[i][j], part[i][j]);
        __syncthreads();
    }

    // t=1024 term: cos rows get (-1)^m * x[1024,e]; sin term is 0
    if (ty < 8) {
        float4 c4 = *(const float4*)&base[(size_t)1024 * 512 + tx * 4];
        float cc[4] = { c4.x, c4.y, c4.z, c4.w };
#pragma unroll
        for (int i = 0; i < 8; i++) {
            int m = ty * 8 + i;
            float sgn = (m & 1) ? -1.f : 1.f;
#pragma unroll
            for (int j = 0; j < 4; j++)
                kadd(acc[i][j], comp[i][j], sgn * cc[j]);
        }
    }

    float* out = dst + (size_t)bh * 8192;
#pragma unroll
    for (int i = 0; i < 8; i++) {
        int m = ty * 8 + i;
        float4 v = make_float4(acc[i][0], acc[i][1], acc[i][2], acc[i][3]);
        *(float4*)&out[m * 64 + tx * 4] = v;
    }
}

// ---------- stage 2: mid. grid 512, block 512, dyn smem ----------
__global__ __launch_bounds__(512) void mid_kernel(const float* __restrict__ w1r,
                                                  const float* __restrict__ w1i) {
    extern __shared__ float smem[];
    float* Qc  = smem;               // -> reused as Vr
    float* Qs  = Qc  + 64 * PIT;     // -> reused as Vi
    float* Kc  = Qs  + 64 * PIT;
    float* Ks  = Kc  + 64 * PIT;
    float* TrT = Ks  + 64 * PIT;     // T transposed: [y][x]
    float* TiT = TrT + 64 * PIT;
    float* Vr  = Qc;
    float* Vi  = Qs;

    int bh = blockIdx.x, h = bh & 7;
    int tid = threadIdx.x;

    {
        const float* qf = g_QF + (size_t)bh * 8192;
        const float* kf = g_KF + (size_t)bh * 8192;
        for (int idx = tid; idx < 4096; idx += 512) {
            int m = idx >> 6, e = idx & 63;
            Qc[m * PIT + e] = qf[idx];
            Qs[m * PIT + e] = qf[4096 + idx];
            Kc[m * PIT + e] = kf[idx];
            Ks[m * PIT + e] = kf[4096 + idx];
        }
    }
    __syncthreads();

    // A[x,y] = sum_e (Qc-iQs)[x]·(Kc-iKs)[y]; T = ctanh(A); store T^T
    {
        int xg = (tid >> 4) * 2;
        int y0 = tid & 15;           // y rows: y0, y0+16, y0+32, y0+48
        float ar[2][4], ai[2][4], car[2][4], cai[2][4];
#pragma unroll
        for (int i = 0; i < 2; i++)
#pragma unroll
            for (int j = 0; j < 4; j++) { ar[i][j] = ai[i][j] = car[i][j] = cai[i][j] = 0.f; }

        for (int e4 = 0; e4 < 64; e4 += 4) {
            float4 qc[2], qs[2], kc[4], ks[4];
#pragma unroll
            for (int i = 0; i < 2; i++) {
                qc[i] = *(float4*)&Qc[(xg + i) * PIT + e4];
                qs[i] = *(float4*)&Qs[(xg + i) * PIT + e4];
            }
#pragma unroll
            for (int j = 0; j < 4; j++) {
                kc[j] = *(float4*)&Kc[(y0 + j * 16) * PIT + e4];
                ks[j] = *(float4*)&Ks[(y0 + j * 16) * PIT + e4];
            }
#pragma unroll
            for (int i = 0; i < 2; i++)
#pragma unroll
                for (int j = 0; j < 4; j++) {
                    float pr = dot4(qc[i], kc[j]) - dot4(qs[i], ks[j]);
                    float pi = dot4(qc[i], ks[j]) + dot4(qs[i], kc[j]);
                    kadd(ar[i][j], car[i][j], pr);
                    kadd(ai[i][j], cai[i][j], -pi);
                }
        }
#pragma unroll
        for (int i = 0; i < 2; i++)
#pragma unroll
            for (int j = 0; j < 4; j++) {
                float a = ar[i][j], bv = ai[i][j];
                float ta = tanhf(a);
                float tb = tanf(bv);
                float ta2 = ta * ta, tb2 = tb * tb;
                float inv = 1.0f / fmaf(ta2, tb2, 1.0f);
                int y = y0 + j * 16;
                TrT[y * PIT + (xg + i)] = ta * (1.0f + tb2) * inv;
                TiT[y * PIT + (xg + i)] = tb * (1.0f - ta2) * inv;
            }
    }
    __syncthreads();

    // V[e,x] = sum_y T[x,y]*(Kc-iKs)[y,e]
    {
        int eg = (tid >> 4) * 2;
        int xg = (tid & 15) * 4;
        float vr0[4] = {0,0,0,0}, vr1[4] = {0,0,0,0};
        float vi0[4] = {0,0,0,0}, vi1[4] = {0,0,0,0};
        for (int y = 0; y < 64; y++) {
            float kc0 = Kc[y * PIT + eg + 0], kc1 = Kc[y * PIT + eg + 1];
            float ks0 = Ks[y * PIT + eg + 0], ks1 = Ks[y * PIT + eg + 1];
            float4 t4 = *(float4*)&TrT[y * PIT + xg];
            float4 u4 = *(float4*)&TiT[y * PIT + xg];
            float tr[4] = { t4.x, t4.y, t4.z, t4.w };
            float ti[4] = { u4.x, u4.y, u4.z, u4.w };
#pragma unroll
            for (int j = 0; j < 4; j++) {
                vr0[j] = fmaf(tr[j], kc0, fmaf( ti[j], ks0, vr0[j]));
                vi0[j] = fmaf(ti[j], kc0, fmaf(-tr[j], ks0, vi0[j]));
                vr1[j] = fmaf(tr[j], kc1, fmaf( ti[j], ks1, vr1[j]));
                vi1[j] = fmaf(ti[j], kc1, fmaf(-tr[j], ks1, vi1[j]));
            }
        }
        __syncthreads();   // everyone done reading old Qc/Qs (aliased by Vr/Vi)
        *(float4*)&Vr[(eg + 0) * PIT + xg] = make_float4(vr0[0], vr0[1], vr0[2], vr0[3]);
        *(float4*)&Vr[(eg + 1) * PIT + xg] = make_float4(vr1[0], vr1[1], vr1[2], vr1[3]);
        *(float4*)&Vi[(eg + 0) * PIT + xg] = make_float4(vi0[0], vi0[1], vi0[2], vi0[3]);
        *(float4*)&Vi[(eg + 1) * PIT + xg] = make_float4(vi1[0], vi1[1], vi1[2], vi1[3]);
    }
    __syncthreads();

    // G[o,x] = sum_e V[e,x]*w1[h,e,o,x]; fold irfft coefficients; write g_G
    {
        int og = (tid >> 4) * 2;
        int xg = (tid & 15) * 4;
        float gr0[4] = {0,0,0,0}, gr1[4] = {0,0,0,0};
        float gi0[4] = {0,0,0,0}, gi1[4] = {0,0,0,0};
        const float* wr = w1r + (size_t)h * 262144;
        const float* wi = w1i + (size_t)h * 262144;
        for (int e = 0; e < 64; e++) {
            float4 a4 = *(float4*)&Vr[e * PIT + xg];
            float4 b4 = *(float4*)&Vi[e * PIT + xg];
            float vr[4] = { a4.x, a4.y, a4.z, a4.w };
            float vi[4] = { b4.x, b4.y, b4.z, b4.w };
            const float* wrb = wr + e * 4096;
            const float* wib = wi + e * 4096;
            float4 r0 = *(const float4*)&wrb[(og + 0) * 64 + xg];
            float4 r1 = *(const float4*)&wrb[(og + 1) * 64 + xg];
            float4 s0 = *(const float4*)&wib[(og + 0) * 64 + xg];
            float4 s1 = *(const float4*)&wib[(og + 1) * 64 + xg];
            float w0r[4] = { r0.x, r0.y, r0.z, r0.w }, w1rr[4] = { r1.x, r1.y, r1.z, r1.w };
            float w0i[4] = { s0.x, s0.y, s0.z, s0.w }, w1ii[4] = { s1.x, s1.y, s1.z, s1.w };
#pragma unroll
            for (int j = 0; j < 4; j++) {
                gr0[j] = fmaf(vr[j], w0r[j],  fmaf(-vi[j], w0i[j],  gr0[j]));
                gi0[j] = fmaf(vr[j], w0i[j],  fmaf( vi[j], w0r[j],  gi0[j]));
                gr1[j] = fmaf(vr[j], w1rr[j], fmaf(-vi[j], w1ii[j], gr1[j]));
                gi1[j] = fmaf(vr[j], w1ii[j], fmaf( vi[j], w1rr[j], gi1[j]));
            }
        }
        const float sc = 1.862645149230957e-09f;  // 1/(2048*512*512)
        float* gout = g_G + (size_t)bh * 8192;
#pragma unroll
        for (int j = 0; j < 4; j++) {
            int m = xg + j;
            float cf = (m == 0) ? sc : 2.0f * sc;
            gout[(og + 0) * 128 + m]      = cf * gr0[j];
            gout[(og + 1) * 128 + m]      = cf * gr1[j];
            gout[(og + 0) * 128 + 64 + m] = -2.0f * sc * gi0[j];
            gout[(og + 1) * 128 + 64 + m] = -2.0f * sc * gi1[j];
        }
    }
}

// ---------- stage 3: folded inverse DFT. grid(8,512) block 256 ----------
// accC = sum_m Gc*cos(ml), accS = sum_m Gs*sin(ml) for l in [l0, l0+128) (l<1024)
// out[l] = accC+accS ; out[2048-l] = accC-accS (l>0) ; out[1024] via (-1)^m epilogue.
__global__ __launch_bounds__(256) void idft_kernel(float* __restrict__ out) {
    int bh = blockIdx.y;
    int l0 = blockIdx.x * 128;
    __shared__ float Gst[128][68];  // [k][o]
    __shared__ float Ws[16][132];   // [k][l]
    int tid = threadIdx.x;
    const float* g = g_G + (size_t)bh * 8192;
#pragma unroll
    for (int jj = 0; jj < 8; jj++) {
        int t4 = tid + jj * 256;          // 2048 float4s
        int o = t4 >> 5, kc = (t4 & 31) * 4;
        float4 v = *(const float4*)&g[o * 128 + kc];
        Gst[kc + 0][o] = v.x; Gst[kc + 1][o] = v.y;
        Gst[kc + 2][o] = v.z; Gst[kc + 3][o] = v.w;
    }

    int ty = tid >> 5, tx = tid & 31;   // 8 o-rows, 4 l-cols
    float accC[8][4], accS[8][4];
#pragma unroll
    for (int i = 0; i < 8; i++)
#pragma unroll
        for (int j = 0; j < 4; j++) { accC[i][j] = 0.f; accS[i][j] = 0.f; }

    for (int k0 = 0; k0 < 128; k0 += 16) {
        __syncthreads();
#pragma unroll
        for (int jj = 0; jj < 2; jj++) {
            int t4 = tid + jj * 256;
            int kk = t4 >> 5, ll = (t4 & 31) * 4;
            *(float4*)&Ws[kk][ll] = *(const float4*)&g_basis[(k0 + kk) * 2048 + l0 + ll];
        }
        __syncthreads();
        if (k0 < 64) {
#pragma unroll
            for (int kk = 0; kk < 16; kk++) {
                float4 w4 = *(float4*)&Ws[kk][tx * 4];
                float wv[4] = { w4.x, w4.y, w4.z, w4.w };
                float a[8];
#pragma unroll
                for (int i = 0; i < 8; i++) a[i] = Gst[k0 + kk][ty * 8 + i];
#pragma unroll
                for (int i = 0; i < 8; i++)
#pragma unroll
                    for (int j = 0; j < 4; j++)
                        accC[i][j] = fmaf(a[i], wv[j], accC[i][j]);
            }
        } else {
#pragma unroll
            for (int kk = 0; kk < 16; kk++) {
                float4 w4 = *(float4*)&Ws[kk][tx * 4];
                float wv[4] = { w4.x, w4.y, w4.z, w4.w };
                float a[8];
#pragma unroll
                for (int i = 0; i < 8; i++) a[i] = Gst[k0 + kk][ty * 8 + i];
#pragma unroll
                for (int i = 0; i < 8; i++)
#pragma unroll
                    for (int j = 0; j < 4; j++)
                        accS[i][j] = fmaf(a[i], wv[j], accS[i][j]);
            }
        }
    }

    float* ob = out + ((size_t)bh * 64) * 2048;
#pragma unroll
    for (int i = 0; i < 8; i++) {
        int o = ty * 8 + i;
        int lb = l0 + tx * 4;
        float4 v = make_float4(accC[i][0] + accS[i][0], accC[i][1] + accS[i][1],
                               accC[i][2] + accS[i][2], accC[i][3] + accS[i][3]);
        *(float4*)&ob[(size_t)o * 2048 + lb] = v;
        // mirror: out[2048-l] = C - S, scalar stores (unaligned), skip l==0
#pragma unroll
        for (int j = 0; j < 4; j++) {
            int l = lb + j;
            if (l > 0)
                ob[(size_t)o * 2048 + (2048 - l)] = accC[i][j] - accS[i][j];
        }
    }

    // l = 1024: out[o,1024] = sum_m Gc[o,m] * (-1)^m   (only one CTA per bh)
    if (blockIdx.x == 0 && tid < 64) {
        int o = tid;
        float s = 0.f;
#pragma unroll
        for (int m = 0; m < 64; m++) {
            float v = Gst[m][o];
            s += (m & 1) ? -v : v;
        }
        ob[(size_t)o * 2048 + 1024] = s;
    }
}

extern "C" void kernel_launch(void* const* d_in, const int* in_sizes, int n_in,
                              void* d_out, int out_size) {
    const float* q   = (const float*)d_in[0];
    const float* k   = (const float*)d_in[1];
    const float* w1r = (const float*)d_in[3];
    const float* w1i = (const float*)d_in[4];
    float* out = (float*)d_out;

    static bool attr_set = false;
    if (!attr_set) {
        cudaFuncSetAttribute(mid_kernel, cudaFuncAttributeMaxDynamicSharedMemorySize, SMEM_MID);
        attr_set = true;
    }

    fill_basis_kernel<<<512, 512>>>();
    dft_kernel<<<dim3(512, 2), 256>>>(q, k);
    mid_kernel<<<512, 512, SMEM_MID>>>(w1r, w1i);
    idft_kernel<<<dim3(8, 512), 256>>>(out);
}

// round 11
// speedup vs baseline: 1.7811x; 1.0838x over previous
#include <cuda_runtime.h>
#include <cuda_bf16.h>
#include <math.h>
#include <stdint.h>

// B=64, L=S=2048, H=8, E=64, MODES=64, O=64. NBH = B*H = 512.
#define PIT 68
#define SMEM_MID (6 * 64 * PIT * 4)

__device__ __align__(16) float g_basis[128 * 2048];   // rows 0-63 cos(2pi m s/2048), 64-127 sin
__device__ __align__(16) float g_QF[512 * 8192];      // per bh: [128 m][64 e]
__device__ __align__(16) float g_KF[512 * 8192];
__device__ __align__(16) float g_G [512 * 8192];      // per bh: [64 o][128 k] folded coeffs
// B' for MMA iDFT: [2048 l][384 k']: [0,128) hi(basis), [128,256) hi(basis), [256,384) lo(basis)
__device__ __align__(16) __nv_bfloat16 g_bstack[2048 * 384];
// A' for MMA iDFT: [256 bhp][128 row][384 k']: [Ghi | Glo | Ghi]
__device__ __align__(16) __nv_bfloat16 g_Astack[256 * 128 * 384];

__global__ void fill_basis_kernel() {
    int idx = blockIdx.x * blockDim.x + threadIdx.x;
    if (idx >= 128 * 2048) return;
    int m = idx >> 11, s = idx & 2047;
    int ph = ((m & 63) * s) & 2047;  // exact integer phase
    double ang = (double)ph * (6.283185307179586476925286766559 / 2048.0);
    g_basis[idx] = (float)((m < 64) ? cos(ang) : sin(ang));
}

__global__ void fill_bstack_kernel() {
    int idx = blockIdx.x * blockDim.x + threadIdx.x;
    if (idx >= 2048 * 384) return;
    int l = idx / 384;
    int kp = idx - l * 384;
    int k = (kp < 128) ? kp : ((kp < 256) ? kp - 128 : kp - 256);
    float v = g_basis[k * 2048 + l];
    __nv_bfloat16 hi = __float2bfloat16(v);
    if (kp < 256) {
        g_bstack[idx] = hi;
    } else {
        g_bstack[idx] = __float2bfloat16(v - __bfloat162float(hi));
    }
}

__global__ void fill_astack_kernel() {
    int idx = blockIdx.x * blockDim.x + threadIdx.x;
    if (idx >= 256 * 128 * 384) return;
    int kp = idx % 384;
    int rest = idx / 384;
    int row = rest & 127;
    int bhp = rest >> 7;
    int t = kp >> 7;         // 0:hi 1:lo 2:hi
    int k = kp & 127;
    int bh = bhp * 2 + (row >> 6);
    int o = row & 63;
    float v = g_G[(size_t)bh * 8192 + o * 128 + k];
    __nv_bfloat16 hi = __float2bfloat16(v);
    g_Astack[idx] = (t == 1) ? __float2bfloat16(v - __bfloat162float(hi)) : hi;
}

__device__ __forceinline__ float dot4(float4 a, float4 b) {
    return a.x * b.x + a.y * b.y + a.z * b.z + a.w * b.w;
}
__device__ __forceinline__ void kadd(float& acc, float& comp, float v) {
    float y = v - comp;
    float t = acc + y;
    comp = (t - acc) - y;
    acc = t;
}
__device__ __forceinline__ uint32_t smem_u32(const void* p) {
    uint32_t a;
    asm("{ .reg .u64 t; cvta.to.shared.u64 t, %1; cvt.u32.u64 %0, t; }" : "=r"(a) : "l"(p));
    return a;
}
#define SWZ128(x) ((x) ^ (((x) >> 3) & 0x70))

__device__ __forceinline__ void cp_async16(uint32_t dst, const void* src) {
    asm volatile("cp.async.cg.shared.global [%0], [%1], 16;" :: "r"(dst), "l"(src));
}
__device__ __forceinline__ void ldsm_x4(uint32_t& r0, uint32_t& r1, uint32_t& r2, uint32_t& r3,
                                        uint32_t addr) {
    asm volatile("ldmatrix.sync.aligned.m8n8.x4.shared.b16 {%0,%1,%2,%3}, [%4];"
                 : "=r"(r0), "=r"(r1), "=r"(r2), "=r"(r3) : "r"(addr));
}
__device__ __forceinline__ void mma16816(float* c, const uint32_t* a, uint32_t b0, uint32_t b1) {
    asm volatile(
        "mma.sync.aligned.m16n8k16.row.col.f32.bf16.bf16.f32 "
        "{%0,%1,%2,%3}, {%4,%5,%6,%7}, {%8,%9}, {%0,%1,%2,%3};"
        : "+f"(c[0]), "+f"(c[1]), "+f"(c[2]), "+f"(c[3])
        : "r"(a[0]), "r"(a[1]), "r"(a[2]), "r"(a[3]), "r"(b0), "r"(b1));
}

// ---------- stage 1: folded forward DFT. grid(512,2) block 256 ----------
__global__ __launch_bounds__(256) void dft_kernel(const float* __restrict__ q,
                                                  const float* __restrict__ k) {
    int bh = blockIdx.x;
    const float* src = blockIdx.y ? k : q;
    float* dst = blockIdx.y ? g_KF : g_QF;
    int b = bh >> 3, h = bh & 7;
    const float* base = src + (size_t)b * 2048 * 512 + (size_t)h * 64;

    __shared__ float Wsm[32][132];
    __shared__ float Ps[32][68];
    __shared__ float Ms[32][68];
    int tid = threadIdx.x;
    int ty = tid >> 4, tx = tid & 15;

    float acc[8][4], comp[8][4];
#pragma unroll
    for (int i = 0; i < 8; i++)
#pragma unroll
        for (int j = 0; j < 4; j++) { acc[i][j] = 0.f; comp[i][j] = 0.f; }

    for (int k0 = 0; k0 < 1024; k0 += 32) {
#pragma unroll
        for (int jj = 0; jj < 4; jj++) {
            int t4 = tid + jj * 256;
            int m = t4 >> 3, kc = (t4 & 7) * 4;
            float4 w = *(const float4*)&g_basis[m * 2048 + k0 + kc];
            Wsm[kc + 0][m] = w.x; Wsm[kc + 1][m] = w.y;
            Wsm[kc + 2][m] = w.z; Wsm[kc + 3][m] = w.w;
        }
#pragma unroll
        for (int jj = 0; jj < 2; jj++) {
            int t4 = tid + jj * 256;
            int l = t4 >> 4, e4 = (t4 & 15) * 4;
            int t = k0 + l;
            float4 fa = *(const float4*)&base[(size_t)t * 512 + e4];
            float4 p, m4;
            if (t == 0) {
                p = fa; m4 = make_float4(0.f, 0.f, 0.f, 0.f);
            } else {
                float4 fb = *(const float4*)&base[(size_t)(2048 - t) * 512 + e4];
                p  = make_float4(fa.x + fb.x, fa.y + fb.y, fa.z + fb.z, fa.w + fb.w);
                m4 = make_float4(fa.x - fb.x, fa.y - fb.y, fa.z - fb.z, fa.w - fb.w);
            }
            *(float4*)&Ps[l][e4] = p;
            *(float4*)&Ms[l][e4] = m4;
        }
        __syncthreads();

        const float (*Xop)[68] = (ty < 8) ? Ps : Ms;
        float part[8][4];
#pragma unroll
        for (int i = 0; i < 8; i++)
#pragma unroll
            for (int j = 0; j < 4; j++) part[i][j] = 0.f;
#pragma unroll
        for (int kk = 0; kk < 32; kk++) {
            float a[8];
#pragma unroll
            for (int i = 0; i < 8; i++) a[i] = Wsm[kk][ty * 8 + i];
            float4 b4 = *(const float4*)&Xop[kk][tx * 4];
            float bb[4] = { b4.x, b4.y, b4.z, b4.w };
#pragma unroll
            for (int i = 0; i < 8; i++)
#pragma unroll
                for (int j = 0; j < 4; j++)
                    part[i][j] = fmaf(a[i], bb[j], part[i][j]);
        }
#pragma unroll
        for (int i = 0; i < 8; i++)
#pragma unroll
            for (int j = 0; j < 4; j++) kadd(acc[i][j], comp[i][j], part[i][j]);
        __syncthreads();
    }

    if (ty < 8) {
        float4 c4 = *(const float4*)&base[(size_t)1024 * 512 + tx * 4];
        float cc[4] = { c4.x, c4.y, c4.z, c4.w };
#pragma unroll
        for (int i = 0; i < 8; i++) {
            int m = ty * 8 + i;
            float sgn = (m & 1) ? -1.f : 1.f;
#pragma unroll
            for (int j = 0; j < 4; j++)
                kadd(acc[i][j], comp[i][j], sgn * cc[j]);
        }
    }

    float* out = dst + (size_t)bh * 8192;
#pragma unroll
    for (int i = 0; i < 8; i++) {
        int m = ty * 8 + i;
        float4 v = make_float4(acc[i][0], acc[i][1], acc[i][2], acc[i][3]);
        *(float4*)&out[m * 64 + tx * 4] = v;
    }
}

// ---------- stage 2: mid. grid 512, block 512, dyn smem ----------
__global__ __launch_bounds__(512) void mid_kernel(const float* __restrict__ w1r,
                                                  const float* __restrict__ w1i) {
    extern __shared__ float smem[];
    float* Qc  = smem;
    float* Qs  = Qc  + 64 * PIT;
    float* Kc  = Qs  + 64 * PIT;
    float* Ks  = Kc  + 64 * PIT;
    float* TrT = Ks  + 64 * PIT;
    float* TiT = TrT + 64 * PIT;
    float* Vr  = Qc;
    float* Vi  = Qs;

    int bh = blockIdx.x, h = bh & 7;
    int tid = threadIdx.x;

    {
        const float* qf = g_QF + (size_t)bh * 8192;
        const float* kf = g_KF + (size_t)bh * 8192;
        for (int idx = tid; idx < 4096; idx += 512) {
            int m = idx >> 6, e = idx & 63;
            Qc[m * PIT + e] = qf[idx];
            Qs[m * PIT + e] = qf[4096 + idx];
            Kc[m * PIT + e] = kf[idx];
            Ks[m * PIT + e] = kf[4096 + idx];
        }
    }
    __syncthreads();

    {
        int xg = (tid >> 4) * 2;
        int y0 = tid & 15;
        float ar[2][4], ai[2][4], car[2][4], cai[2][4];
#pragma unroll
        for (int i = 0; i < 2; i++)
#pragma unroll
            for (int j = 0; j < 4; j++) { ar[i][j] = ai[i][j] = car[i][j] = cai[i][j] = 0.f; }

        for (int e4 = 0; e4 < 64; e4 += 4) {
            float4 qc[2], qs[2], kc[4], ks[4];
#pragma unroll
            for (int i = 0; i < 2; i++) {
                qc[i] = *(float4*)&Qc[(xg + i) * PIT + e4];
                qs[i] = *(float4*)&Qs[(xg + i) * PIT + e4];
            }
#pragma unroll
            for (int j = 0; j < 4; j++) {
                kc[j] = *(float4*)&Kc[(y0 + j * 16) * PIT + e4];
                ks[j] = *(float4*)&Ks[(y0 + j * 16) * PIT + e4];
            }
#pragma unroll
            for (int i = 0; i < 2; i++)
#pragma unroll
                for (int j = 0; j < 4; j++) {
                    float pr = dot4(qc[i], kc[j]) - dot4(qs[i], ks[j]);
                    float pi = dot4(qc[i], ks[j]) + dot4(qs[i], kc[j]);
                    kadd(ar[i][j], car[i][j], pr);
                    kadd(ai[i][j], cai[i][j], -pi);
                }
        }
#pragma unroll
        for (int i = 0; i < 2; i++)
#pragma unroll
            for (int j = 0; j < 4; j++) {
                float a = ar[i][j], bv = ai[i][j];
                float ta = tanhf(a);
                float tb = tanf(bv);
                float ta2 = ta * ta, tb2 = tb * tb;
                float inv = 1.0f / fmaf(ta2, tb2, 1.0f);
                int y = y0 + j * 16;
                TrT[y * PIT + (xg + i)] = ta * (1.0f + tb2) * inv;
                TiT[y * PIT + (xg + i)] = tb * (1.0f - ta2) * inv;
            }
    }
    __syncthreads();

    {
        int eg = (tid >> 4) * 2;
        int xg = (tid & 15) * 4;
        float vr0[4] = {0,0,0,0}, vr1[4] = {0,0,0,0};
        float vi0[4] = {0,0,0,0}, vi1[4] = {0,0,0,0};
        for (int y = 0; y < 64; y++) {
            float kc0 = Kc[y * PIT + eg + 0], kc1 = Kc[y * PIT + eg + 1];
            float ks0 = Ks[y * PIT + eg + 0], ks1 = Ks[y * PIT + eg + 1];
            float4 t4 = *(float4*)&TrT[y * PIT + xg];
            float4 u4 = *(float4*)&TiT[y * PIT + xg];
            float tr[4] = { t4.x, t4.y, t4.z, t4.w };
            float ti[4] = { u4.x, u4.y, u4.z, u4.w };
#pragma unroll
            for (int j = 0; j < 4; j++) {
                vr0[j] = fmaf(tr[j], kc0, fmaf( ti[j], ks0, vr0[j]));
                vi0[j] = fmaf(ti[j], kc0, fmaf(-tr[j], ks0, vi0[j]));
                vr1[j] = fmaf(tr[j], kc1, fmaf( ti[j], ks1, vr1[j]));
                vi1[j] = fmaf(ti[j], kc1, fmaf(-tr[j], ks1, vi1[j]));
            }
        }
        __syncthreads();
        *(float4*)&Vr[(eg + 0) * PIT + xg] = make_float4(vr0[0], vr0[1], vr0[2], vr0[3]);
        *(float4*)&Vr[(eg + 1) * PIT + xg] = make_float4(vr1[0], vr1[1], vr1[2], vr1[3]);
        *(float4*)&Vi[(eg + 0) * PIT + xg] = make_float4(vi0[0], vi0[1], vi0[2], vi0[3]);
        *(float4*)&Vi[(eg + 1) * PIT + xg] = make_float4(vi1[0], vi1[1], vi1[2], vi1[3]);
    }
    __syncthreads();

    {
        int og = (tid >> 4) * 2;
        int xg = (tid & 15) * 4;
        float gr0[4] = {0,0,0,0}, gr1[4] = {0,0,0,0};
        float gi0[4] = {0,0,0,0}, gi1[4] = {0,0,0,0};
        const float* wr = w1r + (size_t)h * 262144;
        const float* wi = w1i + (size_t)h * 262144;
        for (int e = 0; e < 64; e++) {
            float4 a4 = *(float4*)&Vr[e * PIT + xg];
            float4 b4 = *(float4*)&Vi[e * PIT + xg];
            float vr[4] = { a4.x, a4.y, a4.z, a4.w };
            float vi[4] = { b4.x, b4.y, b4.z, b4.w };
            const float* wrb = wr + e * 4096;
            const float* wib = wi + e * 4096;
            float4 r0 = *(const float4*)&wrb[(og + 0) * 64 + xg];
            float4 r1 = *(const float4*)&wrb[(og + 1) * 64 + xg];
            float4 s0 = *(const float4*)&wib[(og + 0) * 64 + xg];
            float4 s1 = *(const float4*)&wib[(og + 1) * 64 + xg];
            float w0r[4] = { r0.x, r0.y, r0.z, r0.w }, w1rr[4] = { r1.x, r1.y, r1.z, r1.w };
            float w0i[4] = { s0.x, s0.y, s0.z, s0.w }, w1ii[4] = { s1.x, s1.y, s1.z, s1.w };
#pragma unroll
            for (int j = 0; j < 4; j++) {
                gr0[j] = fmaf(vr[j], w0r[j],  fmaf(-vi[j], w0i[j],  gr0[j]));
                gi0[j] = fmaf(vr[j], w0i[j],  fmaf( vi[j], w0r[j],  gi0[j]));
                gr1[j] = fmaf(vr[j], w1rr[j], fmaf(-vi[j], w1ii[j], gr1[j]));
                gi1[j] = fmaf(vr[j], w1ii[j], fmaf( vi[j], w1rr[j], gi1[j]));
            }
        }
        const float sc = 1.862645149230957e-09f;  // 1/(2048*512*512)
        float* gout = g_G + (size_t)bh * 8192;
#pragma unroll
        for (int j = 0; j < 4; j++) {
            int m = xg + j;
            float cf = (m == 0) ? sc : 2.0f * sc;
            gout[(og + 0) * 128 + m]      = cf * gr0[j];
            gout[(og + 1) * 128 + m]      = cf * gr1[j];
            gout[(og + 0) * 128 + 64 + m] = -2.0f * sc * gi0[j];
            gout[(og + 1) * 128 + 64 + m] = -2.0f * sc * gi1[j];
        }
    }
}

// ---------- stage 3: mma.sync bf16x3 iDFT GEMM. grid(16, 256), block 256 ----------
// CTA: M=128 (2 bh), N=128 l-cols, K'=384, chunks of 64 double-buffered via cp.async.
#define IDFT_SMEM2 65536

__global__ __launch_bounds__(256) void idft_mma_kernel(float* __restrict__ out) {
    extern __shared__ char sm[];
    uint32_t sb = smem_u32(sm);
    int tid = threadIdx.x;
    int wid = tid >> 5, lane = tid & 31;
    int wm = wid & 3, wn = wid >> 2;       // warp tile: rows wm*32, cols wn*64
    int l0 = blockIdx.x * 128;
    int bhp = blockIdx.y;

    const __nv_bfloat16* Ag = g_Astack + (size_t)bhp * 49152;
    const __nv_bfloat16* Bg = g_bstack + (size_t)l0 * 384;

    float acc[2][8][4];
#pragma unroll
    for (int mi = 0; mi < 2; mi++)
#pragma unroll
        for (int nj = 0; nj < 8; nj++)
#pragma unroll
            for (int t = 0; t < 4; t++) acc[mi][nj][t] = 0.f;

    // buffers: A[buf] @ buf*16384, B[buf] @ 32768 + buf*16384
    auto issue = [&](int c, int buf) {
        for (int i = tid; i < 1024; i += 256) {
            int r = i >> 3, seg = i & 7;
            uint32_t off = (uint32_t)r * 128u + (uint32_t)seg * 16u;
            cp_async16(sb + (uint32_t)buf * 16384u + SWZ128(off),
                       Ag + (size_t)r * 384 + c * 64 + seg * 8);
        }
        for (int i = tid; i < 1024; i += 256) {
            int r = i >> 3, seg = i & 7;
            uint32_t off = (uint32_t)r * 128u + (uint32_t)seg * 16u;
            cp_async16(sb + 32768u + (uint32_t)buf * 16384u + SWZ128(off),
                       Bg + (size_t)r * 384 + c * 64 + seg * 8);
        }
        asm volatile("cp.async.commit_group;");
    };

    issue(0, 0);
    for (int c = 0; c < 6; c++) {
        int buf = c & 1;
        if (c < 5) {
            issue(c + 1, buf ^ 1);
            asm volatile("cp.async.wait_group 1;");
        } else {
            asm volatile("cp.async.wait_group 0;");
        }
        __syncthreads();

        uint32_t abase = sb + (uint32_t)buf * 16384u;
        uint32_t bbase = sb + 32768u + (uint32_t)buf * 16384u;
#pragma unroll
        for (int kk = 0; kk < 4; kk++) {
            uint32_t colb = (uint32_t)kk * 32u + (uint32_t)(lane >> 4) * 16u;
            uint32_t a[2][4];
#pragma unroll
            for (int mi = 0; mi < 2; mi++) {
                uint32_t r = (uint32_t)(wm * 32 + mi * 16 + (lane & 15));
                uint32_t off = r * 128u + colb;
                ldsm_x4(a[mi][0], a[mi][1], a[mi][2], a[mi][3], abase + SWZ128(off));
            }
            uint32_t bf[4][4];
#pragma unroll
            for (int nb = 0; nb < 4; nb++) {
                uint32_t r = (uint32_t)(wn * 64 + nb * 16 + (lane & 15));
                uint32_t off = r * 128u + colb;
                ldsm_x4(bf[nb][0], bf[nb][1], bf[nb][2], bf[nb][3], bbase + SWZ128(off));
            }
#pragma unroll
            for (int mi = 0; mi < 2; mi++)
#pragma unroll
                for (int nb = 0; nb < 4; nb++) {
                    mma16816(acc[mi][nb * 2 + 0], a[mi], bf[nb][0], bf[nb][2]);
                    mma16816(acc[mi][nb * 2 + 1], a[mi], bf[nb][1], bf[nb][3]);
                }
        }
        __syncthreads();
    }

    // epilogue: direct stores, float2 per (row, col-pair); full 32B sectors
    size_t rowbase = (size_t)bhp * 128;
    int g = lane >> 2, t4 = lane & 3;
#pragma unroll
    for (int mi = 0; mi < 2; mi++)
#pragma unroll
        for (int nj = 0; nj < 8; nj++) {
            int r = wm * 32 + mi * 16 + g;
            int cc = wn * 64 + nj * 8 + t4 * 2;
            float2 v0 = make_float2(acc[mi][nj][0], acc[mi][nj][1]);
            float2 v1 = make_float2(acc[mi][nj][2], acc[mi][nj][3]);
            *(float2*)&out[(rowbase + r) * 2048 + (size_t)(l0 + cc)] = v0;
            *(float2*)&out[(rowbase + r + 8) * 2048 + (size_t)(l0 + cc)] = v1;
        }
}

extern "C" void kernel_launch(void* const* d_in, const int* in_sizes, int n_in,
                              void* d_out, int out_size) {
    const float* q   = (const float*)d_in[0];
    const float* k   = (const float*)d_in[1];
    const float* w1r = (const float*)d_in[3];
    const float* w1i = (const float*)d_in[4];
    float* out = (float*)d_out;

    static bool attr_set = false;
    if (!attr_set) {
        cudaFuncSetAttribute(mid_kernel, cudaFuncAttributeMaxDynamicSharedMemorySize, SMEM_MID);
        cudaFuncSetAttribute(idft_mma_kernel, cudaFuncAttributeMaxDynamicSharedMemorySize, IDFT_SMEM2);
        attr_set = true;
    }

    fill_basis_kernel<<<512, 512>>>();
    fill_bstack_kernel<<<3072, 256>>>();
    dft_kernel<<<dim3(512, 2), 256>>>(q, k);
    mid_kernel<<<512, 512, SMEM_MID>>>(w1r, w1i);
    fill_astack_kernel<<<49152, 256>>>();
    idft_mma_kernel<<<dim3(16, 256), 256, IDFT_SMEM2>>>(out);
}

// round 15
// speedup vs baseline: 1.9365x; 1.0872x over previous
#include <cuda_runtime.h>
#include <cuda_bf16.h>
#include <math.h>
#include <stdint.h>

// B=64, L=S=2048, H=8, E=64, MODES=64, O=64. NBH = B*H = 512.
#define PIT 68
#define SMEM_MID (6 * 64 * PIT * 4)

__device__ __align__(16) float g_basis[128 * 2048];   // rows 0-63 cos(2pi m s/2048), 64-127 sin
__device__ __align__(16) float g_QF[512 * 8192];      // per bh: [128 m][64 e]
__device__ __align__(16) float g_KF[512 * 8192];
__device__ __align__(16) float g_G [512 * 8192];      // per bh: [64 o][128 k] folded coeffs
// B' for MMA iDFT: [2048 l][384 k']: [0,128) hi(basis), [128,256) hi(basis), [256,384) lo(basis)
__device__ __align__(16) __nv_bfloat16 g_bstack[2048 * 384];
// A' for MMA iDFT: [256 bhp][128 row][384 k']: [Ghi | Glo | Ghi]
__device__ __align__(16) __nv_bfloat16 g_Astack[256 * 128 * 384];

__global__ void fill_basis_kernel() {
    int idx = blockIdx.x * blockDim.x + threadIdx.x;
    if (idx >= 128 * 2048) return;
    int m = idx >> 11, s = idx & 2047;
    int ph = ((m & 63) * s) & 2047;  // exact integer phase
    double ang = (double)ph * (6.283185307179586476925286766559 / 2048.0);
    g_basis[idx] = (float)((m < 64) ? cos(ang) : sin(ang));
}

__global__ void fill_bstack_kernel() {
    int idx = blockIdx.x * blockDim.x + threadIdx.x;
    if (idx >= 2048 * 384) return;
    int l = idx / 384;
    int kp = idx - l * 384;
    int k = (kp < 128) ? kp : ((kp < 256) ? kp - 128 : kp - 256);
    float v = g_basis[k * 2048 + l];
    __nv_bfloat16 hi = __float2bfloat16(v);
    if (kp < 256) {
        g_bstack[idx] = hi;
    } else {
        g_bstack[idx] = __float2bfloat16(v - __bfloat162float(hi));
    }
}

__global__ void fill_astack_kernel() {
    int idx = blockIdx.x * blockDim.x + threadIdx.x;
    if (idx >= 256 * 128 * 384) return;
    int kp = idx % 384;
    int rest = idx / 384;
    int row = rest & 127;
    int bhp = rest >> 7;
    int t = kp >> 7;         // 0:hi 1:lo 2:hi
    int k = kp & 127;
    int bh = bhp * 2 + (row >> 6);
    int o = row & 63;
    float v = g_G[(size_t)bh * 8192 + o * 128 + k];
    __nv_bfloat16 hi = __float2bfloat16(v);
    g_Astack[idx] = (t == 1) ? __float2bfloat16(v - __bfloat162float(hi)) : hi;
}

__device__ __forceinline__ float dot4(float4 a, float4 b) {
    return a.x * b.x + a.y * b.y + a.z * b.z + a.w * b.w;
}
__device__ __forceinline__ void kadd(float& acc, float& comp, float v) {
    float y = v - comp;
    float t = acc + y;
    comp = (t - acc) - y;
    acc = t;
}
__device__ __forceinline__ uint32_t smem_u32(const void* p) {
    uint32_t a;
    asm("{ .reg .u64 t; cvta.to.shared.u64 t, %1; cvt.u32.u64 %0, t; }" : "=r"(a) : "l"(p));
    return a;
}
#define SWZ128(x) ((x) ^ (((x) >> 3) & 0x70))

// ---- packed f32x2 helpers (Blackwell FFMA2) ----
__device__ __forceinline__ uint64_t pack2(float lo, float hi) {
    uint64_t r;
    asm("mov.b64 %0, {%1, %2};" : "=l"(r) : "f"(lo), "f"(hi));
    return r;
}
__device__ __forceinline__ void ffma2(uint64_t& d, uint64_t a, uint64_t b) {
    asm("fma.rn.f32x2 %0, %1, %2, %0;" : "+l"(d) : "l"(a), "l"(b));
}
__device__ __forceinline__ float2 unpack2(uint64_t v) {
    float2 r;
    asm("mov.b64 {%0, %1}, %2;" : "=f"(r.x), "=f"(r.y) : "l"(v));
    return r;
}

__device__ __forceinline__ void cp_async16(uint32_t dst, const void* src) {
    asm volatile("cp.async.cg.shared.global [%0], [%1], 16;" :: "r"(dst), "l"(src));
}
__device__ __forceinline__ void ldsm_x4(uint32_t& r0, uint32_t& r1, uint32_t& r2, uint32_t& r3,
                                        uint32_t addr) {
    asm volatile("ldmatrix.sync.aligned.m8n8.x4.shared.b16 {%0,%1,%2,%3}, [%4];"
                 : "=r"(r0), "=r"(r1), "=r"(r2), "=r"(r3) : "r"(addr));
}
__device__ __forceinline__ void mma16816(float* c, const uint32_t* a, uint32_t b0, uint32_t b1) {
    asm volatile(
        "mma.sync.aligned.m16n8k16.row.col.f32.bf16.bf16.f32 "
        "{%0,%1,%2,%3}, {%4,%5,%6,%7}, {%8,%9}, {%0,%1,%2,%3};"
        : "+f"(c[0]), "+f"(c[1]), "+f"(c[2]), "+f"(c[3])
        : "r"(a[0]), "r"(a[1]), "r"(a[2]), "r"(a[3]), "r"(b0), "r"(b1));
}

// ---------- stage 1: folded forward DFT (f32x2 packed). grid(512,2) block 256 ----------
__global__ __launch_bounds__(256) void dft_kernel(const float* __restrict__ q,
                                                  const float* __restrict__ k) {
    int bh = blockIdx.x;
    const float* src = blockIdx.y ? k : q;
    float* dst = blockIdx.y ? g_KF : g_QF;
    int b = bh >> 3, h = bh & 7;
    const float* base = src + (size_t)b * 2048 * 512 + (size_t)h * 64;

    __shared__ float Wsm[32][132];
    __shared__ float Ps[32][68];
    __shared__ float Ms[32][68];
    int tid = threadIdx.x;
    int ty = tid >> 4, tx = tid & 15;

    float acc[8][4], comp[8][4];
#pragma unroll
    for (int i = 0; i < 8; i++)
#pragma unroll
        for (int j = 0; j < 4; j++) { acc[i][j] = 0.f; comp[i][j] = 0.f; }

    for (int k0 = 0; k0 < 1024; k0 += 32) {
#pragma unroll
        for (int jj = 0; jj < 4; jj++) {
            int t4 = tid + jj * 256;
            int m = t4 >> 3, kc = (t4 & 7) * 4;
            float4 w = *(const float4*)&g_basis[m * 2048 + k0 + kc];
            Wsm[kc + 0][m] = w.x; Wsm[kc + 1][m] = w.y;
            Wsm[kc + 2][m] = w.z; Wsm[kc + 3][m] = w.w;
        }
#pragma unroll
        for (int jj = 0; jj < 2; jj++) {
            int t4 = tid + jj * 256;
            int l = t4 >> 4, e4 = (t4 & 15) * 4;
            int t = k0 + l;
            float4 fa = *(const float4*)&base[(size_t)t * 512 + e4];
            float4 p, m4;
            if (t == 0) {
                p = fa; m4 = make_float4(0.f, 0.f, 0.f, 0.f);
            } else {
                float4 fb = *(const float4*)&base[(size_t)(2048 - t) * 512 + e4];
                p  = make_float4(fa.x + fb.x, fa.y + fb.y, fa.z + fb.z, fa.w + fb.w);
                m4 = make_float4(fa.x - fb.x, fa.y - fb.y, fa.z - fb.z, fa.w - fb.w);
            }
            *(float4*)&Ps[l][e4] = p;
            *(float4*)&Ms[l][e4] = m4;
        }
        __syncthreads();

        const float (*Xop)[68] = (ty < 8) ? Ps : Ms;
        // packed partials: pair over adjacent m-rows (i = 2p, 2p+1)
        uint64_t part2[4][4];
#pragma unroll
        for (int p = 0; p < 4; p++)
#pragma unroll
            for (int j = 0; j < 4; j++) part2[p][j] = 0ull;
#pragma unroll
        for (int kk = 0; kk < 32; kk++) {
            float4 alo = *(const float4*)&Wsm[kk][ty * 8];
            float4 ahi = *(const float4*)&Wsm[kk][ty * 8 + 4];
            uint64_t ap[4] = { pack2(alo.x, alo.y), pack2(alo.z, alo.w),
                               pack2(ahi.x, ahi.y), pack2(ahi.z, ahi.w) };
            float4 b4 = *(const float4*)&Xop[kk][tx * 4];
            uint64_t bb[4] = { pack2(b4.x, b4.x), pack2(b4.y, b4.y),
                               pack2(b4.z, b4.z), pack2(b4.w, b4.w) };
#pragma unroll
            for (int p = 0; p < 4; p++)
#pragma unroll
                for (int j = 0; j < 4; j++)
                    ffma2(part2[p][j], ap[p], bb[j]);
        }
        // Kahan merge of this K-tile's partial
#pragma unroll
        for (int p = 0; p < 4; p++)
#pragma unroll
            for (int j = 0; j < 4; j++) {
                float2 v = unpack2(part2[p][j]);
                kadd(acc[2 * p + 0][j], comp[2 * p + 0][j], v.x);
                kadd(acc[2 * p + 1][j], comp[2 * p + 1][j], v.y);
            }
        __syncthreads();
    }

    if (ty < 8) {
        float4 c4 = *(const float4*)&base[(size_t)1024 * 512 + tx * 4];
        float cc[4] = { c4.x, c4.y, c4.z, c4.w };
#pragma unroll
        for (int i = 0; i < 8; i++) {
            int m = ty * 8 + i;
            float sgn = (m & 1) ? -1.f : 1.f;
#pragma unroll
            for (int j = 0; j < 4; j++)
                kadd(acc[i][j], comp[i][j], sgn * cc[j]);
        }
    }

    float* out = dst + (size_t)bh * 8192;
#pragma unroll
    for (int i = 0; i < 8; i++) {
        int m = ty * 8 + i;
        float4 v = make_float4(acc[i][0], acc[i][1], acc[i][2], acc[i][3]);
        *(float4*)&out[m * 64 + tx * 4] = v;
    }
}

// ---------- stage 2: mid. grid 512, block 512, dyn smem ----------
__global__ __launch_bounds__(512) void mid_kernel(const float* __restrict__ w1r,
                                                  const float* __restrict__ w1i) {
    extern __shared__ float smem[];
    float* Qc  = smem;
    float* Qs  = Qc  + 64 * PIT;
    float* Kc  = Qs  + 64 * PIT;
    float* Ks  = Kc  + 64 * PIT;
    float* TrT = Ks  + 64 * PIT;
    float* TiT = TrT + 64 * PIT;
    float* Vr  = Qc;
    float* Vi  = Qs;

    int bh = blockIdx.x, h = bh & 7;
    int tid = threadIdx.x;

    {
        const float* qf = g_QF + (size_t)bh * 8192;
        const float* kf = g_KF + (size_t)bh * 8192;
        for (int idx = tid; idx < 4096; idx += 512) {
            int m = idx >> 6, e = idx & 63;
            Qc[m * PIT + e] = qf[idx];
            Qs[m * PIT + e] = qf[4096 + idx];
            Kc[m * PIT + e] = kf[idx];
            Ks[m * PIT + e] = kf[4096 + idx];
        }
    }
    __syncthreads();

    {
        int xg = (tid >> 4) * 2;
        int y0 = tid & 15;
        float ar[2][4], ai[2][4], car[2][4], cai[2][4];
#pragma unroll
        for (int i = 0; i < 2; i++)
#pragma unroll
            for (int j = 0; j < 4; j++) { ar[i][j] = ai[i][j] = car[i][j] = cai[i][j] = 0.f; }

        for (int e4 = 0; e4 < 64; e4 += 4) {
            float4 qc[2], qs[2], kc[4], ks[4];
#pragma unroll
            for (int i = 0; i < 2; i++) {
                qc[i] = *(float4*)&Qc[(xg + i) * PIT + e4];
                qs[i] = *(float4*)&Qs[(xg + i) * PIT + e4];
            }
#pragma unroll
            for (int j = 0; j < 4; j++) {
                kc[j] = *(float4*)&Kc[(y0 + j * 16) * PIT + e4];
                ks[j] = *(float4*)&Ks[(y0 + j * 16) * PIT + e4];
            }
#pragma unroll
            for (int i = 0; i < 2; i++)
#pragma unroll
                for (int j = 0; j < 4; j++) {
                    float pr = dot4(qc[i], kc[j]) - dot4(qs[i], ks[j]);
                    float pi = dot4(qc[i], ks[j]) + dot4(qs[i], kc[j]);
                    kadd(ar[i][j], car[i][j], pr);
                    kadd(ai[i][j], cai[i][j], -pi);
                }
        }
#pragma unroll
        for (int i = 0; i < 2; i++)
#pragma unroll
            for (int j = 0; j < 4; j++) {
                float a = ar[i][j], bv = ai[i][j];
                float ta = tanhf(a);
                float tb = tanf(bv);
                float ta2 = ta * ta, tb2 = tb * tb;
                float inv = 1.0f / fmaf(ta2, tb2, 1.0f);
                int y = y0 + j * 16;
                TrT[y * PIT + (xg + i)] = ta * (1.0f + tb2) * inv;
                TiT[y * PIT + (xg + i)] = tb * (1.0f - ta2) * inv;
            }
    }
    __syncthreads();

    {
        int eg = (tid >> 4) * 2;
        int xg = (tid & 15) * 4;
        float vr0[4] = {0,0,0,0}, vr1[4] = {0,0,0,0};
        float vi0[4] = {0,0,0,0}, vi1[4] = {0,0,0,0};
        for (int y = 0; y < 64; y++) {
            float kc0 = Kc[y * PIT + eg + 0], kc1 = Kc[y * PIT + eg + 1];
            float ks0 = Ks[y * PIT + eg + 0], ks1 = Ks[y * PIT + eg + 1];
            float4 t4 = *(float4*)&TrT[y * PIT + xg];
            float4 u4 = *(float4*)&TiT[y * PIT + xg];
            float tr[4] = { t4.x, t4.y, t4.z, t4.w };
            float ti[4] = { u4.x, u4.y, u4.z, u4.w };
#pragma unroll
            for (int j = 0; j < 4; j++) {
                vr0[j] = fmaf(tr[j], kc0, fmaf( ti[j], ks0, vr0[j]));
                vi0[j] = fmaf(ti[j], kc0, fmaf(-tr[j], ks0, vi0[j]));
                vr1[j] = fmaf(tr[j], kc1, fmaf( ti[j], ks1, vr1[j]));
                vi1[j] = fmaf(ti[j], kc1, fmaf(-tr[j], ks1, vi1[j]));
            }
        }
        __syncthreads();
        *(float4*)&Vr[(eg + 0) * PIT + xg] = make_float4(vr0[0], vr0[1], vr0[2], vr0[3]);
        *(float4*)&Vr[(eg + 1) * PIT + xg] = make_float4(vr1[0], vr1[1], vr1[2], vr1[3]);
        *(float4*)&Vi[(eg + 0) * PIT + xg] = make_float4(vi0[0], vi0[1], vi0[2], vi0[3]);
        *(float4*)&Vi[(eg + 1) * PIT + xg] = make_float4(vi1[0], vi1[1], vi1[2], vi1[3]);
    }
    __syncthreads();

    {
        int og = (tid >> 4) * 2;
        int xg = (tid & 15) * 4;
        float gr0[4] = {0,0,0,0}, gr1[4] = {0,0,0,0};
        float gi0[4] = {0,0,0,0}, gi1[4] = {0,0,0,0};
        const float* wr = w1r + (size_t)h * 262144;
        const float* wi = w1i + (size_t)h * 262144;
        for (int e = 0; e < 64; e++) {
            float4 a4 = *(float4*)&Vr[e * PIT + xg];
            float4 b4 = *(float4*)&Vi[e * PIT + xg];
            float vr[4] = { a4.x, a4.y, a4.z, a4.w };
            float vi[4] = { b4.x, b4.y, b4.z, b4.w };
            const float* wrb = wr + e * 4096;
            const float* wib = wi + e * 4096;
            float4 r0 = *(const float4*)&wrb[(og + 0) * 64 + xg];
            float4 r1 = *(const float4*)&wrb[(og + 1) * 64 + xg];
            float4 s0 = *(const float4*)&wib[(og + 0) * 64 + xg];
            float4 s1 = *(const float4*)&wib[(og + 1) * 64 + xg];
            float w0r[4] = { r0.x, r0.y, r0.z, r0.w }, w1rr[4] = { r1.x, r1.y, r1.z, r1.w };
            float w0i[4] = { s0.x, s0.y, s0.z, s0.w }, w1ii[4] = { s1.x, s1.y, s1.z, s1.w };
#pragma unroll
            for (int j = 0; j < 4; j++) {
                gr0[j] = fmaf(vr[j], w0r[j],  fmaf(-vi[j], w0i[j],  gr0[j]));
                gi0[j] = fmaf(vr[j], w0i[j],  fmaf( vi[j], w0r[j],  gi0[j]));
                gr1[j] = fmaf(vr[j], w1rr[j], fmaf(-vi[j], w1ii[j], gr1[j]));
                gi1[j] = fmaf(vr[j], w1ii[j], fmaf( vi[j], w1rr[j], gi1[j]));
            }
        }
        const float sc = 1.862645149230957e-09f;  // 1/(2048*512*512)
        float* gout = g_G + (size_t)bh * 8192;
#pragma unroll
        for (int j = 0; j < 4; j++) {
            int m = xg + j;
            float cf = (m == 0) ? sc : 2.0f * sc;
            gout[(og + 0) * 128 + m]      = cf * gr0[j];
            gout[(og + 1) * 128 + m]      = cf * gr1[j];
            gout[(og + 0) * 128 + 64 + m] = -2.0f * sc * gi0[j];
            gout[(og + 1) * 128 + 64 + m] = -2.0f * sc * gi1[j];
        }
    }
}

// ---------- stage 3: mma.sync bf16x3 iDFT GEMM. grid(16, 256), block 256 ----------
#define IDFT_SMEM2 65536

__global__ __launch_bounds__(256) void idft_mma_kernel(float* __restrict__ out) {
    extern __shared__ char sm[];
    uint32_t sb = smem_u32(sm);
    int tid = threadIdx.x;
    int wid = tid >> 5, lane = tid & 31;
    int wm = wid & 3, wn = wid >> 2;       // warp tile: rows wm*32, cols wn*64
    int l0 = blockIdx.x * 128;
    int bhp = blockIdx.y;

    const __nv_bfloat16* Ag = g_Astack + (size_t)bhp * 49152;
    const __nv_bfloat16* Bg = g_bstack + (size_t)l0 * 384;

    float acc[2][8][4];
#pragma unroll
    for (int mi = 0; mi < 2; mi++)
#pragma unroll
        for (int nj = 0; nj < 8; nj++)
#pragma unroll
            for (int t = 0; t < 4; t++) acc[mi][nj][t] = 0.f;

    auto issue = [&](int c, int buf) {
        for (int i = tid; i < 1024; i += 256) {
            int r = i >> 3, seg = i & 7;
            uint32_t off = (uint32_t)r * 128u + (uint32_t)seg * 16u;
            cp_async16(sb + (uint32_t)buf * 16384u + SWZ128(off),
                       Ag + (size_t)r * 384 + c * 64 + seg * 8);
        }
        for (int i = tid; i < 1024; i += 256) {
            int r = i >> 3, seg = i & 7;
            uint32_t off = (uint32_t)r * 128u + (uint32_t)seg * 16u;
            cp_async16(sb + 32768u + (uint32_t)buf * 16384u + SWZ128(off),
                       Bg + (size_t)r * 384 + c * 64 + seg * 8);
        }
        asm volatile("cp.async.commit_group;");
    };

    issue(0, 0);
    for (int c = 0; c < 6; c++) {
        int buf = c & 1;
        if (c < 5) {
            issue(c + 1, buf ^ 1);
            asm volatile("cp.async.wait_group 1;");
        } else {
            asm volatile("cp.async.wait_group 0;");
        }
        __syncthreads();

        uint32_t abase = sb + (uint32_t)buf * 16384u;
        uint32_t bbase = sb + 32768u + (uint32_t)buf * 16384u;
#pragma unroll
        for (int kk = 0; kk < 4; kk++) {
            uint32_t colb = (uint32_t)kk * 32u + (uint32_t)(lane >> 4) * 16u;
            uint32_t a[2][4];
#pragma unroll
            for (int mi = 0; mi < 2; mi++) {
                uint32_t r = (uint32_t)(wm * 32 + mi * 16 + (lane & 15));
                uint32_t off = r * 128u + colb;
                ldsm_x4(a[mi][0], a[mi][1], a[mi][2], a[mi][3], abase + SWZ128(off));
            }
            uint32_t bf[4][4];
#pragma unroll
            for (int nb = 0; nb < 4; nb++) {
                uint32_t r = (uint32_t)(wn * 64 + nb * 16 + (lane & 15));
                uint32_t off = r * 128u + colb;
                ldsm_x4(bf[nb][0], bf[nb][1], bf[nb][2], bf[nb][3], bbase + SWZ128(off));
            }
#pragma unroll
            for (int mi = 0; mi < 2; mi++)
#pragma unroll
                for (int nb = 0; nb < 4; nb++) {
                    mma16816(acc[mi][nb * 2 + 0], a[mi], bf[nb][0], bf[nb][2]);
                    mma16816(acc[mi][nb * 2 + 1], a[mi], bf[nb][1], bf[nb][3]);
                }
        }
        __syncthreads();
    }

    size_t rowbase = (size_t)bhp * 128;
    int g = lane >> 2, t4 = lane & 3;
#pragma unroll
    for (int mi = 0; mi < 2; mi++)
#pragma unroll
        for (int nj = 0; nj < 8; nj++) {
            int r = wm * 32 + mi * 16 + g;
            int cc = wn * 64 + nj * 8 + t4 * 2;
            float2 v0 = make_float2(acc[mi][nj][0], acc[mi][nj][1]);
            float2 v1 = make_float2(acc[mi][nj][2], acc[mi][nj][3]);
            *(float2*)&out[(rowbase + r) * 2048 + (size_t)(l0 + cc)] = v0;
            *(float2*)&out[(rowbase + r + 8) * 2048 + (size_t)(l0 + cc)] = v1;
        }
}

extern "C" void kernel_launch(void* const* d_in, const int* in_sizes, int n_in,
                              void* d_out, int out_size) {
    const float* q   = (const float*)d_in[0];
    const float* k   = (const float*)d_in[1];
    const float* w1r = (const float*)d_in[3];
    const float* w1i = (const float*)d_in[4];
    float* out = (float*)d_out;

    static bool attr_set = false;
    if (!attr_set) {
        cudaFuncSetAttribute(mid_kernel, cudaFuncAttributeMaxDynamicSharedMemorySize, SMEM_MID);
        cudaFuncSetAttribute(idft_mma_kernel, cudaFuncAttributeMaxDynamicSharedMemorySize, IDFT_SMEM2);
        attr_set = true;
    }

    fill_basis_kernel<<<512, 512>>>();
    fill_bstack_kernel<<<3072, 256>>>();
    dft_kernel<<<dim3(512, 2), 256>>>(q, k);
    mid_kernel<<<512, 512, SMEM_MID>>>(w1r, w1i);
    fill_astack_kernel<<<49152, 256>>>();
    idft_mma_kernel<<<dim3(16, 256), 256, IDFT_SMEM2>>>(out);
}